// round 4
// baseline (speedup 1.0000x reference)
#include <cuda_runtime.h>
#include <cuda_bf16.h>
#include <math.h>
#include <cstdint>

// ---------------- problem constants ----------------
#define BATCH 2048
#define TT 30
#define ACT 6
#define STOCH 64
#define DETER 1024
#define HIDDEN 1024
#define OUTW (2*STOCH + DETER)   // 1152
#define KIN (STOCH + ACT)        // 70
#define LN_EPS 1e-5f

// ---------------- device state buffers ----------------
__device__ __align__(16) __nv_bfloat16 g_ahi[(size_t)BATCH * 2048];
__device__ __align__(16) __nv_bfloat16 g_alo[(size_t)BATCH * 2048];
__device__ float g_deter[(size_t)BATCH * DETER];
__device__ float g_stoch[(size_t)BATCH * STOCH];
__device__ float g_parts[(size_t)BATCH * 3072];
__device__ float g_e1raw[(size_t)BATCH * 1024];
__device__ __align__(16) __nv_bfloat16 g_wgru_hi[(size_t)3072 * 2048];
__device__ __align__(16) __nv_bfloat16 g_wgru_lo[(size_t)3072 * 2048];
__device__ __align__(16) __nv_bfloat16 g_we1_hi[(size_t)1024 * 1024];
__device__ __align__(16) __nv_bfloat16 g_we1_lo[(size_t)1024 * 1024];

// ---------------- generic helpers ----------------
__device__ __forceinline__ void blockReduce2(float& s, float& ss, float* red) {
    __syncthreads();
#pragma unroll
    for (int o = 16; o > 0; o >>= 1) {
        s  += __shfl_down_sync(0xffffffffu, s, o);
        ss += __shfl_down_sync(0xffffffffu, ss, o);
    }
    int warp = threadIdx.x >> 5, lane = threadIdx.x & 31;
    if (lane == 0) { red[warp] = s; red[8 + warp] = ss; }
    __syncthreads();
    if (threadIdx.x < 32) {
        float a = lane < 8 ? red[lane] : 0.f;
        float c = lane < 8 ? red[8 + lane] : 0.f;
#pragma unroll
        for (int o = 4; o > 0; o >>= 1) {
            a += __shfl_down_sync(0xffffffffu, a, o);
            c += __shfl_down_sync(0xffffffffu, c, o);
        }
        if (lane == 0) { red[0] = a; red[1] = c; }
    }
    __syncthreads();
    s = red[0]; ss = red[1];
}

__device__ __forceinline__ float elu1(float v) { return v > 0.f ? v : expm1f(v); }
__device__ __forceinline__ float sigmoidf(float v) { return 1.f / (1.f + expf(-v)); }

__device__ __forceinline__ void split_store(float v, __nv_bfloat16* hi, __nv_bfloat16* lo) {
    __nv_bfloat16 h = __float2bfloat16(v);
    *hi = h;
    *lo = __float2bfloat16(v - __bfloat162float(h));
}

// ---------------- async-copy + ldmatrix + mma helpers ----------------
__device__ __forceinline__ uint32_t smem_u32(const void* p) {
    return (uint32_t)__cvta_generic_to_shared(p);
}
__device__ __forceinline__ void cpa16(uint32_t dst, const void* src) {
    asm volatile("cp.async.cg.shared.global [%0], [%1], 16;\n" :: "r"(dst), "l"(src));
}
__device__ __forceinline__ void cpa_commit() { asm volatile("cp.async.commit_group;\n" ::: "memory"); }
__device__ __forceinline__ void cpa_wait1()  { asm volatile("cp.async.wait_group 1;\n" ::: "memory"); }
__device__ __forceinline__ void cpa_wait0()  { asm volatile("cp.async.wait_group 0;\n" ::: "memory"); }

#define SWZ(off) ((off) ^ (((off) >> 3) & 0x70))

__device__ __forceinline__ void ldsm_x4(uint32_t* r, uint32_t addr) {
    asm volatile("ldmatrix.sync.aligned.m8n8.x4.shared.b16 {%0,%1,%2,%3}, [%4];"
                 : "=r"(r[0]), "=r"(r[1]), "=r"(r[2]), "=r"(r[3]) : "r"(addr));
}
__device__ __forceinline__ void mma16816(float* c, const uint32_t* a, uint32_t b0, uint32_t b1) {
    asm volatile(
        "mma.sync.aligned.m16n8k16.row.col.f32.bf16.bf16.f32 "
        "{%0,%1,%2,%3}, {%4,%5,%6,%7}, {%8,%9}, {%0,%1,%2,%3};"
        : "+f"(c[0]), "+f"(c[1]), "+f"(c[2]), "+f"(c[3])
        : "r"(a[0]), "r"(a[1]), "r"(a[2]), "r"(a[3]), "r"(b0), "r"(b1));
}

// ---------------- init ----------------
__global__ void init_kernel() {
    int idx = blockIdx.x * blockDim.x + threadIdx.x;
    if (idx < BATCH * DETER) {
        int r = idx >> 10, c = idx & 1023;
        g_deter[idx] = 0.f;
        g_ahi[(size_t)r * 2048 + 1024 + c] = __float2bfloat16(0.f);
        g_alo[(size_t)r * 2048 + 1024 + c] = __float2bfloat16(0.f);
    }
    if (idx < BATCH * STOCH) g_stoch[idx] = 0.f;
}

// ---------------- weight prep: transpose + bf16 hi/lo split (W [K,N] -> Wt [N,K]) ----------------
__global__ __launch_bounds__(256) void wprep_kernel(
    const float* __restrict__ W, __nv_bfloat16* __restrict__ Whi,
    __nv_bfloat16* __restrict__ Wlo, int K, int N)
{
    __shared__ float s[32][33];
    int tx = threadIdx.x & 31, ty = threadIdx.x >> 5;
    int n0 = blockIdx.x * 32, k0 = blockIdx.y * 32;
#pragma unroll
    for (int j = 0; j < 4; j++)
        s[ty + j * 8][tx] = W[(size_t)(k0 + ty + j * 8) * N + n0 + tx];
    __syncthreads();
#pragma unroll
    for (int j = 0; j < 4; j++) {
        int n = n0 + ty + j * 8;
        int k = k0 + tx;
        float v = s[tx][ty + j * 8];
        __nv_bfloat16 h = __float2bfloat16(v);
        Whi[(size_t)n * K + k] = h;
        Wlo[(size_t)n * K + k] = __float2bfloat16(v - __bfloat162float(h));
    }
}

// ---------------- K1: img layer (4 rows/block, grid 512) ----------------
__global__ __launch_bounds__(256) void img_kernel(
    const float* __restrict__ action, const float* __restrict__ W,
    const float* __restrict__ bvec, const float* __restrict__ gvec,
    const float* __restrict__ beta, int t)
{
    __shared__ float xin[4][72];
    __shared__ float vals[4][1024];
    __shared__ float red[64];
    int tid = threadIdx.x;
    int b0 = blockIdx.x * 4;

    for (int e = tid; e < 4 * KIN; e += 256) {
        int r = e / KIN, k = e % KIN;
        xin[r][k] = (k < STOCH) ? g_stoch[(size_t)(b0 + r) * STOCH + k]
                                : action[(size_t)(b0 + r) * (TT * ACT) + t * ACT + (k - STOCH)];
    }
    __syncthreads();

#pragma unroll
    for (int jj = 0; jj < 4; jj++) {
        int j = tid + jj * 256;
        float acc[4];
        float bv = bvec[j];
#pragma unroll
        for (int r = 0; r < 4; r++) acc[r] = bv;
#pragma unroll 2
        for (int k = 0; k < KIN; k++) {
            float w = W[k * 1024 + j];
#pragma unroll
            for (int r = 0; r < 4; r++) acc[r] = fmaf(xin[r][k], w, acc[r]);
        }
#pragma unroll
        for (int r = 0; r < 4; r++) vals[r][j] = acc[r];
    }
    __syncthreads();

    for (int r = 0; r < 4; r++) {
        float s = 0.f, ss = 0.f;
#pragma unroll
        for (int jj = 0; jj < 4; jj++) {
            float v = vals[r][tid + jj * 256];
            s += v; ss += v * v;
        }
        blockReduce2(s, ss, red);
        float mean = s * (1.f / 1024.f);
        float rstd = rsqrtf(ss * (1.f / 1024.f) - mean * mean + LN_EPS);
#pragma unroll
        for (int jj = 0; jj < 4; jj++) {
            int j = tid + jj * 256;
            float v = (vals[r][j] - mean) * rstd * gvec[j] + beta[j];
            float x = elu1(v);
            size_t o = (size_t)(b0 + r) * 2048 + j;
            split_store(x, &g_ahi[o], &g_alo[o]);
        }
    }
}

// ---------------- K2: bf16x3 GEMM via mma.sync, templated on warp-N ----------------
// Block tile 128 x (4*WN); 8 warps = 2(M) x 4(N), warp tile 64 x WN.
// K-slab 64 bf16 (128B rows, XOR swizzle), 2-stage cp.async.
template<int WN, int OCC>
__global__ void __launch_bounds__(256, OCC) mma_gemm_t(int mode)
{
    constexpr int TN = 4 * WN;
    constexpr int NT = WN / 8;           // n8 tiles per warp
    constexpr int NB = WN / 16;          // b ldsm.x4 per kk
    constexpr uint32_t BSTG = TN * 128u; // B bytes per stage
    constexpr uint32_t STG = 16384u + BSTG;

    extern __shared__ char smraw[];
    uint32_t base = smem_u32(smraw);

    const __nv_bfloat16 *Ahi, *Alo, *Bhi, *Blo;
    float* C;
    int lda, ldb, ldc, Kseg;
    if (mode == 0) {
        Ahi = g_ahi; Alo = g_alo; lda = 2048; Kseg = 2048;
        Bhi = g_wgru_hi; Blo = g_wgru_lo; ldb = 2048;
        C = g_parts; ldc = 3072;
    } else {
        Ahi = g_ahi + 1024; Alo = g_alo + 1024; lda = 2048; Kseg = 1024;
        Bhi = g_we1_hi; Blo = g_we1_lo; ldb = 1024;
        C = g_e1raw; ldc = 1024;
    }
    const int slabsPerSeg = Kseg >> 6;
    const int SLABS = 3 * slabsPerSeg;

    int tid = threadIdx.x;
    int wid = tid >> 5, lane = tid & 31;
    int row0 = blockIdx.y * 128;
    int col0 = blockIdx.x * TN;

    float acc[4][NT][4];
#pragma unroll
    for (int i = 0; i < 4; i++)
#pragma unroll
        for (int j = 0; j < NT; j++)
#pragma unroll
            for (int q = 0; q < 4; q++) acc[i][j][q] = 0.f;

    auto load_slab = [&](int s, int buf) {
        int seg = s / slabsPerSeg;
        int k0 = (s - seg * slabsPerSeg) << 6;
        const __nv_bfloat16* As = (seg == 1) ? Alo : Ahi;
        const __nv_bfloat16* Bs = (seg == 2) ? Blo : Bhi;
        uint32_t sA = base + buf * STG;
        uint32_t sB = sA + 16384u;
#pragma unroll
        for (int i = 0; i < 4; i++) {
            int e = tid + i * 256;
            int r = e >> 3, c = e & 7;
            cpa16(sA + SWZ(r * 128 + c * 16), As + (size_t)(row0 + r) * lda + k0 + c * 8);
        }
#pragma unroll
        for (int i = 0; i < TN / 32; i++) {
            int e = tid + i * 256;
            int r = e >> 3, c = e & 7;
            cpa16(sB + SWZ(r * 128 + c * 16), Bs + (size_t)(col0 + r) * ldb + k0 + c * 8);
        }
        cpa_commit();
    };

    int m0w = (wid & 1) * 64;
    int n0w = (wid >> 1) * WN;
    int grp = lane >> 3, rin = lane & 7;

    load_slab(0, 0);

    for (int s = 0; s < SLABS; s++) {
        int buf = s & 1;
        if (s + 1 < SLABS) { load_slab(s + 1, buf ^ 1); cpa_wait1(); }
        else               { cpa_wait0(); }
        __syncthreads();

        uint32_t sA = base + buf * STG;
        uint32_t sB = sA + 16384u;
#pragma unroll
        for (int kk = 0; kk < 4; kk++) {
            int c0 = kk * 2;
            uint32_t a[4][4];
#pragma unroll
            for (int mt = 0; mt < 4; mt++) {
                int row = m0w + mt * 16 + rin + (grp & 1) * 8;
                int ch  = c0 + (grp >> 1);
                ldsm_x4(a[mt], sA + SWZ(row * 128 + ch * 16));
            }
            uint32_t b[NB][4];
#pragma unroll
            for (int nt2 = 0; nt2 < NB; nt2++) {
                int row = n0w + nt2 * 16 + rin + (grp >> 1) * 8;
                int ch  = c0 + (grp & 1);
                ldsm_x4(b[nt2], sB + SWZ(row * 128 + ch * 16));
            }
#pragma unroll
            for (int mt = 0; mt < 4; mt++)
#pragma unroll
                for (int nt = 0; nt < NT; nt++)
                    mma16816(acc[mt][nt], a[mt], b[nt >> 1][(nt & 1) * 2], b[nt >> 1][(nt & 1) * 2 + 1]);
        }
        __syncthreads();
    }

#pragma unroll
    for (int mt = 0; mt < 4; mt++) {
        int r0 = row0 + m0w + mt * 16 + (lane >> 2);
#pragma unroll
        for (int nt = 0; nt < NT; nt++) {
            int cc = col0 + n0w + nt * 8 + (lane & 3) * 2;
            *reinterpret_cast<float2*>(&C[(size_t)r0 * ldc + cc]) =
                make_float2(acc[mt][nt][0], acc[mt][nt][1]);
            *reinterpret_cast<float2*>(&C[(size_t)(r0 + 8) * ldc + cc]) =
                make_float2(acc[mt][nt][2], acc[mt][nt][3]);
        }
    }
}

// ---------------- K3: GRU gates ----------------
__global__ __launch_bounds__(256) void gru_kernel(
    const float* __restrict__ bgru, const float* __restrict__ ggru,
    const float* __restrict__ betag, float* __restrict__ out, int t)
{
    __shared__ float v[3072];
    __shared__ float red[64];
    int b = blockIdx.x, tid = threadIdx.x;
    const float* row = g_parts + (size_t)b * 3072;

    float loc[12];
    float s = 0.f, ss = 0.f;
#pragma unroll
    for (int jj = 0; jj < 12; jj++) {
        int j = tid + jj * 256;
        float x = row[j] + bgru[j];
        loc[jj] = x; s += x; ss += x * x;
    }
    blockReduce2(s, ss, red);
    float mean = s * (1.f / 3072.f);
    float rstd = rsqrtf(ss * (1.f / 3072.f) - mean * mean + LN_EPS);
#pragma unroll
    for (int jj = 0; jj < 12; jj++) {
        int j = tid + jj * 256;
        v[j] = (loc[jj] - mean) * rstd * ggru[j] + betag[j];
    }
    __syncthreads();

#pragma unroll
    for (int jj = 0; jj < 4; jj++) {
        int i = tid + jj * 256;
        float reset  = sigmoidf(v[i]);
        float cand   = tanhf(reset * v[i + 1024]);
        float update = sigmoidf(v[i + 2048] - 1.f);
        float dprev  = g_deter[(size_t)b * 1024 + i];
        float d = update * cand + (1.f - update) * dprev;
        g_deter[(size_t)b * 1024 + i] = d;
        size_t o = (size_t)b * 2048 + 1024 + i;
        split_store(d, &g_ahi[o], &g_alo[o]);
        out[(size_t)b * (TT * OUTW) + (size_t)t * OUTW + 128 + i] = d;
    }
}

// ---------------- K6: fused e1-LN/ELU + e2 GEMM + stats ----------------
// 128 blocks x 256 threads, 16 rows each (rows disjoint across blocks).
__global__ __launch_bounds__(256) void e2_fused_kernel(
    const float* __restrict__ be1, const float* __restrict__ ge1,
    const float* __restrict__ betae1,
    const float* __restrict__ W, const float* __restrict__ bias,
    float* __restrict__ out, int t)
{
    __shared__ float hs[16][33];
    __shared__ float ws[32][128];
    __shared__ float smean[16], srstd[16];
    int tid = threadIdx.x;
    int r0 = blockIdx.x * 16;
    int w = tid >> 5, lane = tid & 31;

    // phase 1: LN stats (each warp: 2 rows)
#pragma unroll
    for (int rr = w * 2; rr < w * 2 + 2; rr++) {
        const float* row = g_e1raw + (size_t)(r0 + rr) * 1024;
        float s = 0.f, ss = 0.f;
#pragma unroll 4
        for (int i = 0; i < 32; i++) {
            int c = i * 32 + lane;
            float x = row[c] + be1[c];
            s += x; ss += x * x;
        }
#pragma unroll
        for (int o = 16; o > 0; o >>= 1) {
            s  += __shfl_down_sync(0xffffffffu, s, o);
            ss += __shfl_down_sync(0xffffffffu, ss, o);
        }
        if (lane == 0) {
            float mean = s * (1.f / 1024.f);
            smean[rr] = mean;
            srstd[rr] = rsqrtf(ss * (1.f / 1024.f) - mean * mean + LN_EPS);
        }
    }
    __syncthreads();

    int col = tid & 127, rl = tid >> 7;
    float acc[8];
#pragma unroll
    for (int q = 0; q < 8; q++) acc[q] = 0.f;

    for (int k0 = 0; k0 < 1024; k0 += 32) {
        for (int e = tid; e < 512; e += 256) {
            int rr = e >> 5, kk = e & 31;
            int c = k0 + kk;
            float x = g_e1raw[(size_t)(r0 + rr) * 1024 + c] + be1[c];
            float v = (x - smean[rr]) * srstd[rr] * ge1[c] + betae1[c];
            hs[rr][kk] = elu1(v);
        }
#pragma unroll
        for (int e = tid; e < 4096; e += 256) {
            int kk = e >> 7, cc = e & 127;
            ws[kk][cc] = W[(size_t)(k0 + kk) * 128 + cc];
        }
        __syncthreads();
#pragma unroll
        for (int kk = 0; kk < 32; kk++) {
            float wv = ws[kk][col];
#pragma unroll
            for (int q = 0; q < 8; q++)
                acc[q] = fmaf(hs[rl + 2 * q][kk], wv, acc[q]);
        }
        __syncthreads();
    }

    float bv = bias[col];
#pragma unroll
    for (int q = 0; q < 8; q++) {
        int r = r0 + rl + 2 * q;
        float sv = acc[q] + bv;
        if (col < 64) {
            g_stoch[(size_t)r * STOCH + col] = sv;
            out[(size_t)r * (TT * OUTW) + (size_t)t * OUTW + col] = sv;
        } else {
            float sp = fmaxf(sv, 0.f) + log1pf(expf(-fabsf(sv)));
            out[(size_t)r * (TT * OUTW) + (size_t)t * OUTW + col] = sp + 0.1f;
        }
    }
}

// ---------------- launcher ----------------
#define MMA_SMEM_GRU 98304
#define MMA_SMEM_E1  65536

extern "C" void kernel_launch(void* const* d_in, const int* in_sizes, int n_in,
                              void* d_out, int out_size)
{
    const float* action   = (const float*)d_in[0];
    const float* W_img    = (const float*)d_in[1];
    const float* b_img    = (const float*)d_in[2];
    const float* g_img    = (const float*)d_in[3];
    const float* beta_img = (const float*)d_in[4];
    const float* W_gru    = (const float*)d_in[5];
    const float* b_gru    = (const float*)d_in[6];
    const float* g_gru    = (const float*)d_in[7];
    const float* beta_gru = (const float*)d_in[8];
    const float* W_e1     = (const float*)d_in[9];    // [5,1024,1024] -> slice 0
    const float* b_e1     = (const float*)d_in[10];
    const float* g_e1     = (const float*)d_in[11];
    const float* beta_e1  = (const float*)d_in[12];
    const float* W_e2     = (const float*)d_in[13];   // [5,1024,128] -> slice 0
    const float* b_e2     = (const float*)d_in[14];
    float* out = (float*)d_out;

    cudaFuncSetAttribute(mma_gemm_t<64, 1>, cudaFuncAttributeMaxDynamicSharedMemorySize, MMA_SMEM_GRU);
    cudaFuncSetAttribute(mma_gemm_t<32, 2>, cudaFuncAttributeMaxDynamicSharedMemorySize, MMA_SMEM_E1);

    init_kernel<<<(BATCH * DETER + 255) / 256, 256>>>();

    __nv_bfloat16 *wgh, *wgl, *weh, *wel;
    cudaGetSymbolAddress((void**)&wgh, g_wgru_hi);
    cudaGetSymbolAddress((void**)&wgl, g_wgru_lo);
    cudaGetSymbolAddress((void**)&weh, g_we1_hi);
    cudaGetSymbolAddress((void**)&wel, g_we1_lo);
    wprep_kernel<<<dim3(3072 / 32, 2048 / 32), 256>>>(W_gru, wgh, wgl, 2048, 3072);
    wprep_kernel<<<dim3(1024 / 32, 1024 / 32), 256>>>(W_e1, weh, wel, 1024, 1024);

    for (int t = 0; t < TT; t++) {
        img_kernel<<<BATCH / 4, 256>>>(action, W_img, b_img, g_img, beta_img, t);
        mma_gemm_t<64, 1><<<dim3(3072 / 256, BATCH / 128), 256, MMA_SMEM_GRU>>>(0);
        gru_kernel<<<BATCH, 256>>>(b_gru, g_gru, beta_gru, out, t);
        mma_gemm_t<32, 2><<<dim3(1024 / 128, BATCH / 128), 256, MMA_SMEM_E1>>>(1);
        e2_fused_kernel<<<BATCH / 16, 256>>>(b_e1, g_e1, beta_e1, W_e2, b_e2, out, t);
    }
}

// round 5
// speedup vs baseline: 1.2730x; 1.2730x over previous
#include <cuda_runtime.h>
#include <cuda_bf16.h>
#include <math.h>
#include <cstdint>

// ---------------- problem constants ----------------
#define BATCH 2048
#define TT 30
#define ACT 6
#define STOCH 64
#define DETER 1024
#define HIDDEN 1024
#define OUTW (2*STOCH + DETER)   // 1152
#define KIN (STOCH + ACT)        // 70
#define LN_EPS 1e-5f

// ---------------- device state buffers ----------------
__device__ __align__(16) __nv_bfloat16 g_ahi[(size_t)BATCH * 2048];
__device__ __align__(16) __nv_bfloat16 g_alo[(size_t)BATCH * 2048];
__device__ float g_deter[(size_t)BATCH * DETER];
__device__ float g_stoch[(size_t)BATCH * STOCH];
__device__ float g_parts[(size_t)BATCH * 3072];
__device__ float g_e1raw[(size_t)BATCH * 1024];
__device__ __align__(16) __nv_bfloat16 g_wgru_hi[(size_t)3072 * 2048];
__device__ __align__(16) __nv_bfloat16 g_wgru_lo[(size_t)3072 * 2048];
__device__ __align__(16) __nv_bfloat16 g_we1_hi[(size_t)1024 * 1024];
__device__ __align__(16) __nv_bfloat16 g_we1_lo[(size_t)1024 * 1024];

// ---------------- generic helpers ----------------
__device__ __forceinline__ void blockReduce2(float& s, float& ss, float* red) {
    __syncthreads();
#pragma unroll
    for (int o = 16; o > 0; o >>= 1) {
        s  += __shfl_down_sync(0xffffffffu, s, o);
        ss += __shfl_down_sync(0xffffffffu, ss, o);
    }
    int warp = threadIdx.x >> 5, lane = threadIdx.x & 31;
    if (lane == 0) { red[warp] = s; red[8 + warp] = ss; }
    __syncthreads();
    if (threadIdx.x < 32) {
        float a = lane < 8 ? red[lane] : 0.f;
        float c = lane < 8 ? red[8 + lane] : 0.f;
#pragma unroll
        for (int o = 4; o > 0; o >>= 1) {
            a += __shfl_down_sync(0xffffffffu, a, o);
            c += __shfl_down_sync(0xffffffffu, c, o);
        }
        if (lane == 0) { red[0] = a; red[1] = c; }
    }
    __syncthreads();
    s = red[0]; ss = red[1];
}

__device__ __forceinline__ float elu1(float v) { return v > 0.f ? v : expm1f(v); }
__device__ __forceinline__ float sigmoidf(float v) { return 1.f / (1.f + expf(-v)); }

__device__ __forceinline__ void split_store(float v, __nv_bfloat16* hi, __nv_bfloat16* lo) {
    __nv_bfloat16 h = __float2bfloat16(v);
    *hi = h;
    *lo = __float2bfloat16(v - __bfloat162float(h));
}

// ---------------- async-copy + ldmatrix + mma helpers ----------------
__device__ __forceinline__ uint32_t smem_u32(const void* p) {
    return (uint32_t)__cvta_generic_to_shared(p);
}
__device__ __forceinline__ void cpa16(uint32_t dst, const void* src) {
    asm volatile("cp.async.cg.shared.global [%0], [%1], 16;\n" :: "r"(dst), "l"(src));
}
__device__ __forceinline__ void cpa_commit() { asm volatile("cp.async.commit_group;\n" ::: "memory"); }
__device__ __forceinline__ void cpa_wait1()  { asm volatile("cp.async.wait_group 1;\n" ::: "memory"); }
__device__ __forceinline__ void cpa_wait0()  { asm volatile("cp.async.wait_group 0;\n" ::: "memory"); }

#define SWZ(off) ((off) ^ (((off) >> 3) & 0x70))

__device__ __forceinline__ void ldsm_x4(uint32_t* r, uint32_t addr) {
    asm volatile("ldmatrix.sync.aligned.m8n8.x4.shared.b16 {%0,%1,%2,%3}, [%4];"
                 : "=r"(r[0]), "=r"(r[1]), "=r"(r[2]), "=r"(r[3]) : "r"(addr));
}
__device__ __forceinline__ void mma16816(float* c, const uint32_t* a, uint32_t b0, uint32_t b1) {
    asm volatile(
        "mma.sync.aligned.m16n8k16.row.col.f32.bf16.bf16.f32 "
        "{%0,%1,%2,%3}, {%4,%5,%6,%7}, {%8,%9}, {%0,%1,%2,%3};"
        : "+f"(c[0]), "+f"(c[1]), "+f"(c[2]), "+f"(c[3])
        : "r"(a[0]), "r"(a[1]), "r"(a[2]), "r"(a[3]), "r"(b0), "r"(b1));
}

// ---------------- init ----------------
__global__ void init_kernel() {
    int idx = blockIdx.x * blockDim.x + threadIdx.x;
    if (idx < BATCH * DETER) {
        int r = idx >> 10, c = idx & 1023;
        g_deter[idx] = 0.f;
        g_ahi[(size_t)r * 2048 + 1024 + c] = __float2bfloat16(0.f);
        g_alo[(size_t)r * 2048 + 1024 + c] = __float2bfloat16(0.f);
    }
    if (idx < BATCH * STOCH) g_stoch[idx] = 0.f;
}

// ---------------- weight prep: transpose + bf16 hi/lo split (W [K,N] -> Wt [N,K]) ----------------
__global__ __launch_bounds__(256) void wprep_kernel(
    const float* __restrict__ W, __nv_bfloat16* __restrict__ Whi,
    __nv_bfloat16* __restrict__ Wlo, int K, int N)
{
    __shared__ float s[32][33];
    int tx = threadIdx.x & 31, ty = threadIdx.x >> 5;
    int n0 = blockIdx.x * 32, k0 = blockIdx.y * 32;
#pragma unroll
    for (int j = 0; j < 4; j++)
        s[ty + j * 8][tx] = W[(size_t)(k0 + ty + j * 8) * N + n0 + tx];
    __syncthreads();
#pragma unroll
    for (int j = 0; j < 4; j++) {
        int n = n0 + ty + j * 8;
        int k = k0 + tx;
        float v = s[tx][ty + j * 8];
        __nv_bfloat16 h = __float2bfloat16(v);
        Whi[(size_t)n * K + k] = h;
        Wlo[(size_t)n * K + k] = __float2bfloat16(v - __bfloat162float(h));
    }
}

// ---------------- K1: img layer (8 rows/block, float4 W loads) ----------------
__global__ __launch_bounds__(256) void img_kernel(
    const float* __restrict__ action, const float* __restrict__ W,
    const float* __restrict__ bvec, const float* __restrict__ gvec,
    const float* __restrict__ beta, int t)
{
    __shared__ float xin[8][72];
    __shared__ float vals[8][1024];
    __shared__ float red[64];
    int tid = threadIdx.x;
    int b0 = blockIdx.x * 8;

    for (int e = tid; e < 8 * KIN; e += 256) {
        int r = e / KIN, k = e % KIN;
        xin[r][k] = (k < STOCH) ? g_stoch[(size_t)(b0 + r) * STOCH + k]
                                : action[(size_t)(b0 + r) * (TT * ACT) + t * ACT + (k - STOCH)];
    }
    __syncthreads();

    // each thread owns 4 consecutive output columns j0..j0+3
    {
        int j0 = tid * 4;
        float acc[8][4];
        float4 bv = *reinterpret_cast<const float4*>(&bvec[j0]);
#pragma unroll
        for (int r = 0; r < 8; r++) {
            acc[r][0] = bv.x; acc[r][1] = bv.y; acc[r][2] = bv.z; acc[r][3] = bv.w;
        }
        for (int k = 0; k < KIN; k++) {
            float4 w = *reinterpret_cast<const float4*>(&W[k * 1024 + j0]);
#pragma unroll
            for (int r = 0; r < 8; r++) {
                float xv = xin[r][k];
                acc[r][0] = fmaf(xv, w.x, acc[r][0]);
                acc[r][1] = fmaf(xv, w.y, acc[r][1]);
                acc[r][2] = fmaf(xv, w.z, acc[r][2]);
                acc[r][3] = fmaf(xv, w.w, acc[r][3]);
            }
        }
#pragma unroll
        for (int r = 0; r < 8; r++)
            *reinterpret_cast<float4*>(&vals[r][j0]) =
                make_float4(acc[r][0], acc[r][1], acc[r][2], acc[r][3]);
    }
    __syncthreads();

    for (int r = 0; r < 8; r++) {
        float s = 0.f, ss = 0.f;
#pragma unroll
        for (int jj = 0; jj < 4; jj++) {
            float v = vals[r][tid + jj * 256];
            s += v; ss += v * v;
        }
        blockReduce2(s, ss, red);
        float mean = s * (1.f / 1024.f);
        float rstd = rsqrtf(ss * (1.f / 1024.f) - mean * mean + LN_EPS);
#pragma unroll
        for (int jj = 0; jj < 4; jj++) {
            int j = tid + jj * 256;
            float v = (vals[r][j] - mean) * rstd * gvec[j] + beta[j];
            float x = elu1(v);
            size_t o = (size_t)(b0 + r) * 2048 + j;
            split_store(x, &g_ahi[o], &g_alo[o]);
        }
    }
}

// ---------------- K2: bf16x3 GEMM via mma.sync (HMMA), R3-proven shape ----------------
// Block tile 128x128, 8 warps = 2(M) x 4(N), warp tile 64x32.
// K-slab 64 bf16 (128B rows, XOR swizzle), 2-stage cp.async, occ 2.
__global__ __launch_bounds__(256, 2) void mma_gemm(int mode)
{
    extern __shared__ char smraw[];
    uint32_t base = smem_u32(smraw);

    const __nv_bfloat16 *Ahi, *Alo, *Bhi, *Blo;
    float* C;
    int lda, ldb, ldc, Kseg;
    if (mode == 0) {
        Ahi = g_ahi; Alo = g_alo; lda = 2048; Kseg = 2048;
        Bhi = g_wgru_hi; Blo = g_wgru_lo; ldb = 2048;
        C = g_parts; ldc = 3072;
    } else {
        Ahi = g_ahi + 1024; Alo = g_alo + 1024; lda = 2048; Kseg = 1024;
        Bhi = g_we1_hi; Blo = g_we1_lo; ldb = 1024;
        C = g_e1raw; ldc = 1024;
    }
    const int slabsPerSeg = Kseg >> 6;
    const int SLABS = 3 * slabsPerSeg;

    int tid = threadIdx.x;
    int wid = tid >> 5, lane = tid & 31;
    int row0 = blockIdx.y * 128;
    int col0 = blockIdx.x * 128;

    const uint32_t STG = 32768u;

    float acc[4][4][4];
#pragma unroll
    for (int i = 0; i < 4; i++)
#pragma unroll
        for (int j = 0; j < 4; j++)
#pragma unroll
            for (int q = 0; q < 4; q++) acc[i][j][q] = 0.f;

    auto load_slab = [&](int s, int buf) {
        int seg = s / slabsPerSeg;
        int k0 = (s - seg * slabsPerSeg) << 6;
        const __nv_bfloat16* As = (seg == 1) ? Alo : Ahi;
        const __nv_bfloat16* Bs = (seg == 2) ? Blo : Bhi;
        uint32_t sA = base + buf * STG;
        uint32_t sB = sA + 16384u;
#pragma unroll
        for (int i = 0; i < 4; i++) {
            int e = tid + i * 256;
            int r = e >> 3, c = e & 7;
            cpa16(sA + SWZ(r * 128 + c * 16), As + (size_t)(row0 + r) * lda + k0 + c * 8);
        }
#pragma unroll
        for (int i = 0; i < 4; i++) {
            int e = tid + i * 256;
            int r = e >> 3, c = e & 7;
            cpa16(sB + SWZ(r * 128 + c * 16), Bs + (size_t)(col0 + r) * ldb + k0 + c * 8);
        }
        cpa_commit();
    };

    int m0w = (wid & 1) * 64;
    int n0w = (wid >> 1) * 32;
    int grp = lane >> 3, rin = lane & 7;

    load_slab(0, 0);

    for (int s = 0; s < SLABS; s++) {
        int buf = s & 1;
        if (s + 1 < SLABS) { load_slab(s + 1, buf ^ 1); cpa_wait1(); }
        else               { cpa_wait0(); }
        __syncthreads();

        uint32_t sA = base + buf * STG;
        uint32_t sB = sA + 16384u;
#pragma unroll
        for (int kk = 0; kk < 4; kk++) {
            int c0 = kk * 2;
            uint32_t a[4][4];
#pragma unroll
            for (int mt = 0; mt < 4; mt++) {
                int row = m0w + mt * 16 + rin + (grp & 1) * 8;
                int ch  = c0 + (grp >> 1);
                ldsm_x4(a[mt], sA + SWZ(row * 128 + ch * 16));
            }
            uint32_t b[2][4];
#pragma unroll
            for (int nt2 = 0; nt2 < 2; nt2++) {
                int row = n0w + nt2 * 16 + rin + (grp >> 1) * 8;
                int ch  = c0 + (grp & 1);
                ldsm_x4(b[nt2], sB + SWZ(row * 128 + ch * 16));
            }
#pragma unroll
            for (int mt = 0; mt < 4; mt++)
#pragma unroll
                for (int nt = 0; nt < 4; nt++)
                    mma16816(acc[mt][nt], a[mt], b[nt >> 1][(nt & 1) * 2], b[nt >> 1][(nt & 1) * 2 + 1]);
        }
        __syncthreads();
    }

#pragma unroll
    for (int mt = 0; mt < 4; mt++) {
        int r0 = row0 + m0w + mt * 16 + (lane >> 2);
#pragma unroll
        for (int nt = 0; nt < 4; nt++) {
            int cc = col0 + n0w + nt * 8 + (lane & 3) * 2;
            *reinterpret_cast<float2*>(&C[(size_t)r0 * ldc + cc]) =
                make_float2(acc[mt][nt][0], acc[mt][nt][1]);
            *reinterpret_cast<float2*>(&C[(size_t)(r0 + 8) * ldc + cc]) =
                make_float2(acc[mt][nt][2], acc[mt][nt][3]);
        }
    }
}

// ---------------- K3: GRU gates ----------------
__global__ __launch_bounds__(256) void gru_kernel(
    const float* __restrict__ bgru, const float* __restrict__ ggru,
    const float* __restrict__ betag, float* __restrict__ out, int t)
{
    __shared__ float v[3072];
    __shared__ float red[64];
    int b = blockIdx.x, tid = threadIdx.x;
    const float* row = g_parts + (size_t)b * 3072;

    float loc[12];
    float s = 0.f, ss = 0.f;
#pragma unroll
    for (int jj = 0; jj < 12; jj++) {
        int j = tid + jj * 256;
        float x = row[j] + bgru[j];
        loc[jj] = x; s += x; ss += x * x;
    }
    blockReduce2(s, ss, red);
    float mean = s * (1.f / 3072.f);
    float rstd = rsqrtf(ss * (1.f / 3072.f) - mean * mean + LN_EPS);
#pragma unroll
    for (int jj = 0; jj < 12; jj++) {
        int j = tid + jj * 256;
        v[j] = (loc[jj] - mean) * rstd * ggru[j] + betag[j];
    }
    __syncthreads();

#pragma unroll
    for (int jj = 0; jj < 4; jj++) {
        int i = tid + jj * 256;
        float reset  = sigmoidf(v[i]);
        float cand   = tanhf(reset * v[i + 1024]);
        float update = sigmoidf(v[i + 2048] - 1.f);
        float dprev  = g_deter[(size_t)b * 1024 + i];
        float d = update * cand + (1.f - update) * dprev;
        g_deter[(size_t)b * 1024 + i] = d;
        size_t o = (size_t)b * 2048 + 1024 + i;
        split_store(d, &g_ahi[o], &g_alo[o]);
        out[(size_t)b * (TT * OUTW) + (size_t)t * OUTW + 128 + i] = d;
    }
}

// ---------------- K6: fused e1-LN/ELU + e2 GEMM + stats ----------------
__global__ __launch_bounds__(256) void e2_fused_kernel(
    const float* __restrict__ be1, const float* __restrict__ ge1,
    const float* __restrict__ betae1,
    const float* __restrict__ W, const float* __restrict__ bias,
    float* __restrict__ out, int t)
{
    __shared__ float hs[16][33];
    __shared__ float ws[32][128];
    __shared__ float smean[16], srstd[16];
    int tid = threadIdx.x;
    int r0 = blockIdx.x * 16;
    int w = tid >> 5, lane = tid & 31;

#pragma unroll
    for (int rr = w * 2; rr < w * 2 + 2; rr++) {
        const float* row = g_e1raw + (size_t)(r0 + rr) * 1024;
        float s = 0.f, ss = 0.f;
#pragma unroll 4
        for (int i = 0; i < 32; i++) {
            int c = i * 32 + lane;
            float x = row[c] + be1[c];
            s += x; ss += x * x;
        }
#pragma unroll
        for (int o = 16; o > 0; o >>= 1) {
            s  += __shfl_down_sync(0xffffffffu, s, o);
            ss += __shfl_down_sync(0xffffffffu, ss, o);
        }
        if (lane == 0) {
            float mean = s * (1.f / 1024.f);
            smean[rr] = mean;
            srstd[rr] = rsqrtf(ss * (1.f / 1024.f) - mean * mean + LN_EPS);
        }
    }
    __syncthreads();

    int col = tid & 127, rl = tid >> 7;
    float acc[8];
#pragma unroll
    for (int q = 0; q < 8; q++) acc[q] = 0.f;

    for (int k0 = 0; k0 < 1024; k0 += 32) {
        for (int e = tid; e < 512; e += 256) {
            int rr = e >> 5, kk = e & 31;
            int c = k0 + kk;
            float x = g_e1raw[(size_t)(r0 + rr) * 1024 + c] + be1[c];
            float v = (x - smean[rr]) * srstd[rr] * ge1[c] + betae1[c];
            hs[rr][kk] = elu1(v);
        }
#pragma unroll
        for (int e = tid; e < 4096; e += 256) {
            int kk = e >> 7, cc = e & 127;
            ws[kk][cc] = W[(size_t)(k0 + kk) * 128 + cc];
        }
        __syncthreads();
#pragma unroll
        for (int kk = 0; kk < 32; kk++) {
            float wv = ws[kk][col];
#pragma unroll
            for (int q = 0; q < 8; q++)
                acc[q] = fmaf(hs[rl + 2 * q][kk], wv, acc[q]);
        }
        __syncthreads();
    }

    float bv = bias[col];
#pragma unroll
    for (int q = 0; q < 8; q++) {
        int r = r0 + rl + 2 * q;
        float sv = acc[q] + bv;
        if (col < 64) {
            g_stoch[(size_t)r * STOCH + col] = sv;
            out[(size_t)r * (TT * OUTW) + (size_t)t * OUTW + col] = sv;
        } else {
            float sp = fmaxf(sv, 0.f) + log1pf(expf(-fabsf(sv)));
            out[(size_t)r * (TT * OUTW) + (size_t)t * OUTW + col] = sp + 0.1f;
        }
    }
}

// ---------------- launcher ----------------
#define MMA_SMEM 65536

extern "C" void kernel_launch(void* const* d_in, const int* in_sizes, int n_in,
                              void* d_out, int out_size)
{
    const float* action   = (const float*)d_in[0];
    const float* W_img    = (const float*)d_in[1];
    const float* b_img    = (const float*)d_in[2];
    const float* g_img    = (const float*)d_in[3];
    const float* beta_img = (const float*)d_in[4];
    const float* W_gru    = (const float*)d_in[5];
    const float* b_gru    = (const float*)d_in[6];
    const float* g_gru    = (const float*)d_in[7];
    const float* beta_gru = (const float*)d_in[8];
    const float* W_e1     = (const float*)d_in[9];    // [5,1024,1024] -> slice 0
    const float* b_e1     = (const float*)d_in[10];
    const float* g_e1     = (const float*)d_in[11];
    const float* beta_e1  = (const float*)d_in[12];
    const float* W_e2     = (const float*)d_in[13];   // [5,1024,128] -> slice 0
    const float* b_e2     = (const float*)d_in[14];
    float* out = (float*)d_out;

    cudaFuncSetAttribute(mma_gemm, cudaFuncAttributeMaxDynamicSharedMemorySize, MMA_SMEM);

    init_kernel<<<(BATCH * DETER + 255) / 256, 256>>>();

    __nv_bfloat16 *wgh, *wgl, *weh, *wel;
    cudaGetSymbolAddress((void**)&wgh, g_wgru_hi);
    cudaGetSymbolAddress((void**)&wgl, g_wgru_lo);
    cudaGetSymbolAddress((void**)&weh, g_we1_hi);
    cudaGetSymbolAddress((void**)&wel, g_we1_lo);
    wprep_kernel<<<dim3(3072 / 32, 2048 / 32), 256>>>(W_gru, wgh, wgl, 2048, 3072);
    wprep_kernel<<<dim3(1024 / 32, 1024 / 32), 256>>>(W_e1, weh, wel, 1024, 1024);

    for (int t = 0; t < TT; t++) {
        img_kernel<<<BATCH / 8, 256>>>(action, W_img, b_img, g_img, beta_img, t);
        mma_gemm<<<dim3(3072 / 128, BATCH / 128), 256, MMA_SMEM>>>(0);
        gru_kernel<<<BATCH, 256>>>(b_gru, g_gru, beta_gru, out, t);
        mma_gemm<<<dim3(1024 / 128, BATCH / 128), 256, MMA_SMEM>>>(1);
        e2_fused_kernel<<<BATCH / 16, 256>>>(b_e1, g_e1, beta_e1, W_e2, b_e2, out, t);
    }
}

// round 6
// speedup vs baseline: 1.3313x; 1.0458x over previous
#include <cuda_runtime.h>
#include <cuda_bf16.h>
#include <math.h>
#include <cstdint>

// ---------------- problem constants ----------------
#define BATCH 2048
#define TT 30
#define ACT 6
#define STOCH 64
#define DETER 1024
#define HIDDEN 1024
#define OUTW (2*STOCH + DETER)   // 1152
#define KIN (STOCH + ACT)        // 70
#define LN_EPS 1e-5f

// ---------------- device state buffers ----------------
__device__ __align__(16) __nv_bfloat16 g_ahi[(size_t)BATCH * 2048];
__device__ __align__(16) __nv_bfloat16 g_alo[(size_t)BATCH * 2048];
__device__ float g_deter[(size_t)BATCH * DETER];
__device__ float g_stoch[(size_t)BATCH * STOCH];
__device__ float g_parts[(size_t)BATCH * 3072];
__device__ float g_e1raw[(size_t)BATCH * 1024];
__device__ float g_h[(size_t)BATCH * 1024];
__device__ __align__(16) __nv_bfloat16 g_wgru_hi[(size_t)3072 * 2048];
__device__ __align__(16) __nv_bfloat16 g_wgru_lo[(size_t)3072 * 2048];
__device__ __align__(16) __nv_bfloat16 g_we1_hi[(size_t)1024 * 1024];
__device__ __align__(16) __nv_bfloat16 g_we1_lo[(size_t)1024 * 1024];

// ---------------- generic helpers ----------------
__device__ __forceinline__ void blockReduce2(float& s, float& ss, float* red) {
    __syncthreads();
#pragma unroll
    for (int o = 16; o > 0; o >>= 1) {
        s  += __shfl_down_sync(0xffffffffu, s, o);
        ss += __shfl_down_sync(0xffffffffu, ss, o);
    }
    int warp = threadIdx.x >> 5, lane = threadIdx.x & 31;
    if (lane == 0) { red[warp] = s; red[8 + warp] = ss; }
    __syncthreads();
    if (threadIdx.x < 32) {
        float a = lane < 8 ? red[lane] : 0.f;
        float c = lane < 8 ? red[8 + lane] : 0.f;
#pragma unroll
        for (int o = 4; o > 0; o >>= 1) {
            a += __shfl_down_sync(0xffffffffu, a, o);
            c += __shfl_down_sync(0xffffffffu, c, o);
        }
        if (lane == 0) { red[0] = a; red[1] = c; }
    }
    __syncthreads();
    s = red[0]; ss = red[1];
}

__device__ __forceinline__ float elu1(float v) { return v > 0.f ? v : expm1f(v); }
__device__ __forceinline__ float sigmoidf(float v) { return 1.f / (1.f + expf(-v)); }

__device__ __forceinline__ void split_store(float v, __nv_bfloat16* hi, __nv_bfloat16* lo) {
    __nv_bfloat16 h = __float2bfloat16(v);
    *hi = h;
    *lo = __float2bfloat16(v - __bfloat162float(h));
}

// ---------------- async-copy + ldmatrix + mma helpers ----------------
__device__ __forceinline__ uint32_t smem_u32(const void* p) {
    return (uint32_t)__cvta_generic_to_shared(p);
}
__device__ __forceinline__ void cpa16(uint32_t dst, const void* src) {
    asm volatile("cp.async.cg.shared.global [%0], [%1], 16;\n" :: "r"(dst), "l"(src));
}
__device__ __forceinline__ void cpa_commit() { asm volatile("cp.async.commit_group;\n" ::: "memory"); }
__device__ __forceinline__ void cpa_wait1()  { asm volatile("cp.async.wait_group 1;\n" ::: "memory"); }
__device__ __forceinline__ void cpa_wait0()  { asm volatile("cp.async.wait_group 0;\n" ::: "memory"); }

#define SWZ(off) ((off) ^ (((off) >> 3) & 0x70))

__device__ __forceinline__ void ldsm_x4(uint32_t* r, uint32_t addr) {
    asm volatile("ldmatrix.sync.aligned.m8n8.x4.shared.b16 {%0,%1,%2,%3}, [%4];"
                 : "=r"(r[0]), "=r"(r[1]), "=r"(r[2]), "=r"(r[3]) : "r"(addr));
}
__device__ __forceinline__ void mma16816(float* c, const uint32_t* a, uint32_t b0, uint32_t b1) {
    asm volatile(
        "mma.sync.aligned.m16n8k16.row.col.f32.bf16.bf16.f32 "
        "{%0,%1,%2,%3}, {%4,%5,%6,%7}, {%8,%9}, {%0,%1,%2,%3};"
        : "+f"(c[0]), "+f"(c[1]), "+f"(c[2]), "+f"(c[3])
        : "r"(a[0]), "r"(a[1]), "r"(a[2]), "r"(a[3]), "r"(b0), "r"(b1));
}

// ---------------- init ----------------
__global__ void init_kernel() {
    int idx = blockIdx.x * blockDim.x + threadIdx.x;
    if (idx < BATCH * DETER) {
        int r = idx >> 10, c = idx & 1023;
        g_deter[idx] = 0.f;
        g_ahi[(size_t)r * 2048 + 1024 + c] = __float2bfloat16(0.f);
        g_alo[(size_t)r * 2048 + 1024 + c] = __float2bfloat16(0.f);
    }
    if (idx < BATCH * STOCH) g_stoch[idx] = 0.f;
}

// ---------------- weight prep: transpose + bf16 hi/lo split (W [K,N] -> Wt [N,K]) ----------------
__global__ __launch_bounds__(256) void wprep_kernel(
    const float* __restrict__ W, __nv_bfloat16* __restrict__ Whi,
    __nv_bfloat16* __restrict__ Wlo, int K, int N)
{
    __shared__ float s[32][33];
    int tx = threadIdx.x & 31, ty = threadIdx.x >> 5;
    int n0 = blockIdx.x * 32, k0 = blockIdx.y * 32;
#pragma unroll
    for (int j = 0; j < 4; j++)
        s[ty + j * 8][tx] = W[(size_t)(k0 + ty + j * 8) * N + n0 + tx];
    __syncthreads();
#pragma unroll
    for (int j = 0; j < 4; j++) {
        int n = n0 + ty + j * 8;
        int k = k0 + tx;
        float v = s[tx][ty + j * 8];
        __nv_bfloat16 h = __float2bfloat16(v);
        Whi[(size_t)n * K + k] = h;
        Wlo[(size_t)n * K + k] = __float2bfloat16(v - __bfloat162float(h));
    }
}

// ---------------- K1: img layer (8 rows/block, float4 W loads) ----------------
__global__ __launch_bounds__(256) void img_kernel(
    const float* __restrict__ action, const float* __restrict__ W,
    const float* __restrict__ bvec, const float* __restrict__ gvec,
    const float* __restrict__ beta, int t)
{
    __shared__ float xin[8][72];
    __shared__ float vals[8][1024];
    __shared__ float red[64];
    int tid = threadIdx.x;
    int b0 = blockIdx.x * 8;

    for (int e = tid; e < 8 * KIN; e += 256) {
        int r = e / KIN, k = e % KIN;
        xin[r][k] = (k < STOCH) ? g_stoch[(size_t)(b0 + r) * STOCH + k]
                                : action[(size_t)(b0 + r) * (TT * ACT) + t * ACT + (k - STOCH)];
    }
    __syncthreads();

    {
        int j0 = tid * 4;
        float acc[8][4];
        float4 bv = *reinterpret_cast<const float4*>(&bvec[j0]);
#pragma unroll
        for (int r = 0; r < 8; r++) {
            acc[r][0] = bv.x; acc[r][1] = bv.y; acc[r][2] = bv.z; acc[r][3] = bv.w;
        }
        for (int k = 0; k < KIN; k++) {
            float4 w = *reinterpret_cast<const float4*>(&W[k * 1024 + j0]);
#pragma unroll
            for (int r = 0; r < 8; r++) {
                float xv = xin[r][k];
                acc[r][0] = fmaf(xv, w.x, acc[r][0]);
                acc[r][1] = fmaf(xv, w.y, acc[r][1]);
                acc[r][2] = fmaf(xv, w.z, acc[r][2]);
                acc[r][3] = fmaf(xv, w.w, acc[r][3]);
            }
        }
#pragma unroll
        for (int r = 0; r < 8; r++)
            *reinterpret_cast<float4*>(&vals[r][j0]) =
                make_float4(acc[r][0], acc[r][1], acc[r][2], acc[r][3]);
    }
    __syncthreads();

    for (int r = 0; r < 8; r++) {
        float s = 0.f, ss = 0.f;
#pragma unroll
        for (int jj = 0; jj < 4; jj++) {
            float v = vals[r][tid + jj * 256];
            s += v; ss += v * v;
        }
        blockReduce2(s, ss, red);
        float mean = s * (1.f / 1024.f);
        float rstd = rsqrtf(ss * (1.f / 1024.f) - mean * mean + LN_EPS);
#pragma unroll
        for (int jj = 0; jj < 4; jj++) {
            int j = tid + jj * 256;
            float v = (vals[r][j] - mean) * rstd * gvec[j] + beta[j];
            float x = elu1(v);
            size_t o = (size_t)(b0 + r) * 2048 + j;
            split_store(x, &g_ahi[o], &g_alo[o]);
        }
    }
}

// ---------------- K2: bf16x3 GEMM via mma.sync (HMMA), 3-stage pipeline ----------------
// Block tile 128x128, 8 warps = 2(M) x 4(N), warp tile 64x32.
// K-slab 64 bf16 (128B rows, XOR swizzle), 3-stage cp.async (96KB smem), occ 2.
__global__ __launch_bounds__(256, 2) void mma_gemm(int mode)
{
    extern __shared__ char smraw[];
    uint32_t base = smem_u32(smraw);

    const __nv_bfloat16 *Ahi, *Alo, *Bhi, *Blo;
    float* C;
    int lda, ldb, ldc, Kseg;
    if (mode == 0) {
        Ahi = g_ahi; Alo = g_alo; lda = 2048; Kseg = 2048;
        Bhi = g_wgru_hi; Blo = g_wgru_lo; ldb = 2048;
        C = g_parts; ldc = 3072;
    } else {
        Ahi = g_ahi + 1024; Alo = g_alo + 1024; lda = 2048; Kseg = 1024;
        Bhi = g_we1_hi; Blo = g_we1_lo; ldb = 1024;
        C = g_e1raw; ldc = 1024;
    }
    const int slabsPerSeg = Kseg >> 6;
    const int SLABS = 3 * slabsPerSeg;

    int tid = threadIdx.x;
    int wid = tid >> 5, lane = tid & 31;
    int row0 = blockIdx.y * 128;
    int col0 = blockIdx.x * 128;

    const uint32_t STG = 32768u;

    float acc[4][4][4];
#pragma unroll
    for (int i = 0; i < 4; i++)
#pragma unroll
        for (int j = 0; j < 4; j++)
#pragma unroll
            for (int q = 0; q < 4; q++) acc[i][j][q] = 0.f;

    auto load_slab = [&](int s, int buf) {
        int seg = s / slabsPerSeg;
        int k0 = (s - seg * slabsPerSeg) << 6;
        const __nv_bfloat16* As = (seg == 1) ? Alo : Ahi;
        const __nv_bfloat16* Bs = (seg == 2) ? Blo : Bhi;
        uint32_t sA = base + (uint32_t)buf * STG;
        uint32_t sB = sA + 16384u;
#pragma unroll
        for (int i = 0; i < 4; i++) {
            int e = tid + i * 256;
            int r = e >> 3, c = e & 7;
            cpa16(sA + SWZ(r * 128 + c * 16), As + (size_t)(row0 + r) * lda + k0 + c * 8);
        }
#pragma unroll
        for (int i = 0; i < 4; i++) {
            int e = tid + i * 256;
            int r = e >> 3, c = e & 7;
            cpa16(sB + SWZ(r * 128 + c * 16), Bs + (size_t)(col0 + r) * ldb + k0 + c * 8);
        }
        cpa_commit();
    };

    int m0w = (wid & 1) * 64;
    int n0w = (wid >> 1) * 32;
    int grp = lane >> 3, rin = lane & 7;

    // 3-stage: preload slabs 0,1
    load_slab(0, 0);
    load_slab(1, 1);

    for (int s = 0; s < SLABS; s++) {
        int buf = s % 3;
        if (s + 1 < SLABS) cpa_wait1();   // 2 groups in flight -> slab s done
        else               cpa_wait0();   // last slab: drain
        __syncthreads();

        // refill the buffer freed at iteration s-1 with slab s+2
        if (s + 2 < SLABS) load_slab(s + 2, (s + 2) % 3);

        uint32_t sA = base + (uint32_t)buf * STG;
        uint32_t sB = sA + 16384u;
#pragma unroll
        for (int kk = 0; kk < 4; kk++) {
            int c0 = kk * 2;
            uint32_t a[4][4];
#pragma unroll
            for (int mt = 0; mt < 4; mt++) {
                int row = m0w + mt * 16 + rin + (grp & 1) * 8;
                int ch  = c0 + (grp >> 1);
                ldsm_x4(a[mt], sA + SWZ(row * 128 + ch * 16));
            }
            uint32_t b[2][4];
#pragma unroll
            for (int nt2 = 0; nt2 < 2; nt2++) {
                int row = n0w + nt2 * 16 + rin + (grp >> 1) * 8;
                int ch  = c0 + (grp & 1);
                ldsm_x4(b[nt2], sB + SWZ(row * 128 + ch * 16));
            }
#pragma unroll
            for (int mt = 0; mt < 4; mt++)
#pragma unroll
                for (int nt = 0; nt < 4; nt++)
                    mma16816(acc[mt][nt], a[mt], b[nt >> 1][(nt & 1) * 2], b[nt >> 1][(nt & 1) * 2 + 1]);
        }
        __syncthreads();
    }

#pragma unroll
    for (int mt = 0; mt < 4; mt++) {
        int r0 = row0 + m0w + mt * 16 + (lane >> 2);
#pragma unroll
        for (int nt = 0; nt < 4; nt++) {
            int cc = col0 + n0w + nt * 8 + (lane & 3) * 2;
            *reinterpret_cast<float2*>(&C[(size_t)r0 * ldc + cc]) =
                make_float2(acc[mt][nt][0], acc[mt][nt][1]);
            *reinterpret_cast<float2*>(&C[(size_t)(r0 + 8) * ldc + cc]) =
                make_float2(acc[mt][nt][2], acc[mt][nt][3]);
        }
    }
}

// ---------------- K3: GRU gates ----------------
__global__ __launch_bounds__(256) void gru_kernel(
    const float* __restrict__ bgru, const float* __restrict__ ggru,
    const float* __restrict__ betag, float* __restrict__ out, int t)
{
    __shared__ float v[3072];
    __shared__ float red[64];
    int b = blockIdx.x, tid = threadIdx.x;
    const float* row = g_parts + (size_t)b * 3072;

    float loc[12];
    float s = 0.f, ss = 0.f;
#pragma unroll
    for (int jj = 0; jj < 12; jj++) {
        int j = tid + jj * 256;
        float x = row[j] + bgru[j];
        loc[jj] = x; s += x; ss += x * x;
    }
    blockReduce2(s, ss, red);
    float mean = s * (1.f / 3072.f);
    float rstd = rsqrtf(ss * (1.f / 3072.f) - mean * mean + LN_EPS);
#pragma unroll
    for (int jj = 0; jj < 12; jj++) {
        int j = tid + jj * 256;
        v[j] = (loc[jj] - mean) * rstd * ggru[j] + betag[j];
    }
    __syncthreads();

#pragma unroll
    for (int jj = 0; jj < 4; jj++) {
        int i = tid + jj * 256;
        float reset  = sigmoidf(v[i]);
        float cand   = tanhf(reset * v[i + 1024]);
        float update = sigmoidf(v[i + 2048] - 1.f);
        float dprev  = g_deter[(size_t)b * 1024 + i];
        float d = update * cand + (1.f - update) * dprev;
        g_deter[(size_t)b * 1024 + i] = d;
        size_t o = (size_t)b * 2048 + 1024 + i;
        split_store(d, &g_ahi[o], &g_alo[o]);
        out[(size_t)b * (TT * OUTW) + (size_t)t * OUTW + 128 + i] = d;
    }
}

// ---------------- K5: e1 LN+ELU ----------------
__global__ __launch_bounds__(256) void e1ln_kernel(
    const float* __restrict__ be1, const float* __restrict__ ge1,
    const float* __restrict__ betae1)
{
    __shared__ float red[64];
    int b = blockIdx.x, tid = threadIdx.x;
    float loc[4];
    float s = 0.f, ss = 0.f;
#pragma unroll
    for (int jj = 0; jj < 4; jj++) {
        int j = tid + jj * 256;
        float x = g_e1raw[(size_t)b * 1024 + j] + be1[j];
        loc[jj] = x; s += x; ss += x * x;
    }
    blockReduce2(s, ss, red);
    float mean = s * (1.f / 1024.f);
    float rstd = rsqrtf(ss * (1.f / 1024.f) - mean * mean + LN_EPS);
#pragma unroll
    for (int jj = 0; jj < 4; jj++) {
        int j = tid + jj * 256;
        float v = (loc[jj] - mean) * rstd * ge1[j] + betae1[j];
        g_h[(size_t)b * 1024 + j] = elu1(v);
    }
}

// ---------------- K6: e2 GEMM + stats ----------------
__global__ __launch_bounds__(256) void e2_kernel(
    const float* __restrict__ W, const float* __restrict__ bias,
    float* __restrict__ out, int t)
{
    __shared__ float hs[16][33];
    __shared__ float ws[32][128];
    int tid = threadIdx.x;
    int r0 = blockIdx.x * 16;
    int col = tid & 127, rl = tid >> 7;
    float acc[8];
#pragma unroll
    for (int q = 0; q < 8; q++) acc[q] = 0.f;

    for (int k0 = 0; k0 < 1024; k0 += 32) {
        for (int e = tid; e < 512; e += 256) {
            int rr = e >> 5, kk = e & 31;
            hs[rr][kk] = g_h[(size_t)(r0 + rr) * 1024 + k0 + kk];
        }
#pragma unroll
        for (int e = tid; e < 4096; e += 256) {
            int kk = e >> 7, cc = e & 127;
            ws[kk][cc] = W[(size_t)(k0 + kk) * 128 + cc];
        }
        __syncthreads();
#pragma unroll
        for (int kk = 0; kk < 32; kk++) {
            float wv = ws[kk][col];
#pragma unroll
            for (int q = 0; q < 8; q++)
                acc[q] = fmaf(hs[rl + 2 * q][kk], wv, acc[q]);
        }
        __syncthreads();
    }

    float bv = bias[col];
#pragma unroll
    for (int q = 0; q < 8; q++) {
        int r = r0 + rl + 2 * q;
        float sv = acc[q] + bv;
        if (col < 64) {
            g_stoch[(size_t)r * STOCH + col] = sv;
            out[(size_t)r * (TT * OUTW) + (size_t)t * OUTW + col] = sv;
        } else {
            float sp = fmaxf(sv, 0.f) + log1pf(expf(-fabsf(sv)));
            out[(size_t)r * (TT * OUTW) + (size_t)t * OUTW + col] = sp + 0.1f;
        }
    }
}

// ---------------- launcher ----------------
#define MMA_SMEM 98304

extern "C" void kernel_launch(void* const* d_in, const int* in_sizes, int n_in,
                              void* d_out, int out_size)
{
    const float* action   = (const float*)d_in[0];
    const float* W_img    = (const float*)d_in[1];
    const float* b_img    = (const float*)d_in[2];
    const float* g_img    = (const float*)d_in[3];
    const float* beta_img = (const float*)d_in[4];
    const float* W_gru    = (const float*)d_in[5];
    const float* b_gru    = (const float*)d_in[6];
    const float* g_gru    = (const float*)d_in[7];
    const float* beta_gru = (const float*)d_in[8];
    const float* W_e1     = (const float*)d_in[9];    // [5,1024,1024] -> slice 0
    const float* b_e1     = (const float*)d_in[10];
    const float* g_e1     = (const float*)d_in[11];
    const float* beta_e1  = (const float*)d_in[12];
    const float* W_e2     = (const float*)d_in[13];   // [5,1024,128] -> slice 0
    const float* b_e2     = (const float*)d_in[14];
    float* out = (float*)d_out;

    cudaFuncSetAttribute(mma_gemm, cudaFuncAttributeMaxDynamicSharedMemorySize, MMA_SMEM);

    init_kernel<<<(BATCH * DETER + 255) / 256, 256>>>();

    __nv_bfloat16 *wgh, *wgl, *weh, *wel;
    cudaGetSymbolAddress((void**)&wgh, g_wgru_hi);
    cudaGetSymbolAddress((void**)&wgl, g_wgru_lo);
    cudaGetSymbolAddress((void**)&weh, g_we1_hi);
    cudaGetSymbolAddress((void**)&wel, g_we1_lo);
    wprep_kernel<<<dim3(3072 / 32, 2048 / 32), 256>>>(W_gru, wgh, wgl, 2048, 3072);
    wprep_kernel<<<dim3(1024 / 32, 1024 / 32), 256>>>(W_e1, weh, wel, 1024, 1024);

    for (int t = 0; t < TT; t++) {
        img_kernel<<<BATCH / 8, 256>>>(action, W_img, b_img, g_img, beta_img, t);
        mma_gemm<<<dim3(3072 / 128, BATCH / 128), 256, MMA_SMEM>>>(0);
        gru_kernel<<<BATCH, 256>>>(b_gru, g_gru, beta_gru, out, t);
        mma_gemm<<<dim3(1024 / 128, BATCH / 128), 256, MMA_SMEM>>>(1);
        e1ln_kernel<<<BATCH, 256>>>(b_e1, g_e1, beta_e1);
        e2_kernel<<<BATCH / 16, 256>>>(W_e2, b_e2, out, t);
    }
}

// round 7
// speedup vs baseline: 1.3628x; 1.0237x over previous
#include <cuda_runtime.h>
#include <cuda_bf16.h>
#include <math.h>
#include <cstdint>

// ---------------- problem constants ----------------
#define BATCH 2048
#define TT 30
#define ACT 6
#define STOCH 64
#define DETER 1024
#define HIDDEN 1024
#define OUTW (2*STOCH + DETER)   // 1152
#define KIN (STOCH + ACT)        // 70
#define LN_EPS 1e-5f

// ---------------- device state buffers ----------------
__device__ __align__(16) __nv_bfloat16 g_ahi[(size_t)BATCH * 2048];
__device__ __align__(16) __nv_bfloat16 g_alo[(size_t)BATCH * 2048];
__device__ float g_deter[(size_t)BATCH * DETER];
__device__ float g_stoch[(size_t)BATCH * STOCH];
__device__ float g_parts[(size_t)BATCH * 3072];
__device__ float g_e1raw[(size_t)BATCH * 1024];
__device__ float g_h[(size_t)BATCH * 1024];
__device__ __align__(16) __nv_bfloat16 g_wgru_hi[(size_t)3072 * 2048];
__device__ __align__(16) __nv_bfloat16 g_wgru_lo[(size_t)3072 * 2048];
__device__ __align__(16) __nv_bfloat16 g_we1_hi[(size_t)1024 * 1024];
__device__ __align__(16) __nv_bfloat16 g_we1_lo[(size_t)1024 * 1024];

// ---------------- generic helpers ----------------
__device__ __forceinline__ void blockReduce2(float& s, float& ss, float* red) {
    __syncthreads();
#pragma unroll
    for (int o = 16; o > 0; o >>= 1) {
        s  += __shfl_down_sync(0xffffffffu, s, o);
        ss += __shfl_down_sync(0xffffffffu, ss, o);
    }
    int warp = threadIdx.x >> 5, lane = threadIdx.x & 31;
    if (lane == 0) { red[warp] = s; red[8 + warp] = ss; }
    __syncthreads();
    if (threadIdx.x < 32) {
        float a = lane < 8 ? red[lane] : 0.f;
        float c = lane < 8 ? red[8 + lane] : 0.f;
#pragma unroll
        for (int o = 4; o > 0; o >>= 1) {
            a += __shfl_down_sync(0xffffffffu, a, o);
            c += __shfl_down_sync(0xffffffffu, c, o);
        }
        if (lane == 0) { red[0] = a; red[1] = c; }
    }
    __syncthreads();
    s = red[0]; ss = red[1];
}

__device__ __forceinline__ float elu1(float v) { return v > 0.f ? v : expm1f(v); }
__device__ __forceinline__ float sigmoidf(float v) { return 1.f / (1.f + expf(-v)); }

__device__ __forceinline__ void split_store(float v, __nv_bfloat16* hi, __nv_bfloat16* lo) {
    __nv_bfloat16 h = __float2bfloat16(v);
    *hi = h;
    *lo = __float2bfloat16(v - __bfloat162float(h));
}

// ---------------- async-copy + ldmatrix + mma helpers ----------------
__device__ __forceinline__ uint32_t smem_u32(const void* p) {
    return (uint32_t)__cvta_generic_to_shared(p);
}
__device__ __forceinline__ void cpa16(uint32_t dst, const void* src) {
    asm volatile("cp.async.cg.shared.global [%0], [%1], 16;\n" :: "r"(dst), "l"(src));
}
__device__ __forceinline__ void cpa_commit() { asm volatile("cp.async.commit_group;\n" ::: "memory"); }
__device__ __forceinline__ void cpa_wait1()  { asm volatile("cp.async.wait_group 1;\n" ::: "memory"); }
__device__ __forceinline__ void cpa_wait0()  { asm volatile("cp.async.wait_group 0;\n" ::: "memory"); }

// 64B-row swizzle: XOR 16B-chunk index (bits 5:4) with row bits 2:1 (bits 8:7)
#define SWZ64(off) ((off) ^ (((off) >> 3) & 0x30))

__device__ __forceinline__ void ldsm_x4(uint32_t* r, uint32_t addr) {
    asm volatile("ldmatrix.sync.aligned.m8n8.x4.shared.b16 {%0,%1,%2,%3}, [%4];"
                 : "=r"(r[0]), "=r"(r[1]), "=r"(r[2]), "=r"(r[3]) : "r"(addr));
}
__device__ __forceinline__ void mma16816(float* c, const uint32_t* a, uint32_t b0, uint32_t b1) {
    asm volatile(
        "mma.sync.aligned.m16n8k16.row.col.f32.bf16.bf16.f32 "
        "{%0,%1,%2,%3}, {%4,%5,%6,%7}, {%8,%9}, {%0,%1,%2,%3};"
        : "+f"(c[0]), "+f"(c[1]), "+f"(c[2]), "+f"(c[3])
        : "r"(a[0]), "r"(a[1]), "r"(a[2]), "r"(a[3]), "r"(b0), "r"(b1));
}

// ---------------- init ----------------
__global__ void init_kernel() {
    int idx = blockIdx.x * blockDim.x + threadIdx.x;
    if (idx < BATCH * DETER) {
        int r = idx >> 10, c = idx & 1023;
        g_deter[idx] = 0.f;
        g_ahi[(size_t)r * 2048 + 1024 + c] = __float2bfloat16(0.f);
        g_alo[(size_t)r * 2048 + 1024 + c] = __float2bfloat16(0.f);
    }
    if (idx < BATCH * STOCH) g_stoch[idx] = 0.f;
}

// ---------------- weight prep: transpose + bf16 hi/lo split (W [K,N] -> Wt [N,K]) ----------------
__global__ __launch_bounds__(256) void wprep_kernel(
    const float* __restrict__ W, __nv_bfloat16* __restrict__ Whi,
    __nv_bfloat16* __restrict__ Wlo, int K, int N)
{
    __shared__ float s[32][33];
    int tx = threadIdx.x & 31, ty = threadIdx.x >> 5;
    int n0 = blockIdx.x * 32, k0 = blockIdx.y * 32;
#pragma unroll
    for (int j = 0; j < 4; j++)
        s[ty + j * 8][tx] = W[(size_t)(k0 + ty + j * 8) * N + n0 + tx];
    __syncthreads();
#pragma unroll
    for (int j = 0; j < 4; j++) {
        int n = n0 + ty + j * 8;
        int k = k0 + tx;
        float v = s[tx][ty + j * 8];
        __nv_bfloat16 h = __float2bfloat16(v);
        Whi[(size_t)n * K + k] = h;
        Wlo[(size_t)n * K + k] = __float2bfloat16(v - __bfloat162float(h));
    }
}

// ---------------- K1: img layer (8 rows/block, float4 W loads) ----------------
__global__ __launch_bounds__(256) void img_kernel(
    const float* __restrict__ action, const float* __restrict__ W,
    const float* __restrict__ bvec, const float* __restrict__ gvec,
    const float* __restrict__ beta, int t)
{
    __shared__ float xin[8][72];
    __shared__ float vals[8][1024];
    __shared__ float red[64];
    int tid = threadIdx.x;
    int b0 = blockIdx.x * 8;

    for (int e = tid; e < 8 * KIN; e += 256) {
        int r = e / KIN, k = e % KIN;
        xin[r][k] = (k < STOCH) ? g_stoch[(size_t)(b0 + r) * STOCH + k]
                                : action[(size_t)(b0 + r) * (TT * ACT) + t * ACT + (k - STOCH)];
    }
    __syncthreads();

    {
        int j0 = tid * 4;
        float acc[8][4];
        float4 bv = *reinterpret_cast<const float4*>(&bvec[j0]);
#pragma unroll
        for (int r = 0; r < 8; r++) {
            acc[r][0] = bv.x; acc[r][1] = bv.y; acc[r][2] = bv.z; acc[r][3] = bv.w;
        }
        for (int k = 0; k < KIN; k++) {
            float4 w = *reinterpret_cast<const float4*>(&W[k * 1024 + j0]);
#pragma unroll
            for (int r = 0; r < 8; r++) {
                float xv = xin[r][k];
                acc[r][0] = fmaf(xv, w.x, acc[r][0]);
                acc[r][1] = fmaf(xv, w.y, acc[r][1]);
                acc[r][2] = fmaf(xv, w.z, acc[r][2]);
                acc[r][3] = fmaf(xv, w.w, acc[r][3]);
            }
        }
#pragma unroll
        for (int r = 0; r < 8; r++)
            *reinterpret_cast<float4*>(&vals[r][j0]) =
                make_float4(acc[r][0], acc[r][1], acc[r][2], acc[r][3]);
    }
    __syncthreads();

    for (int r = 0; r < 8; r++) {
        float s = 0.f, ss = 0.f;
#pragma unroll
        for (int jj = 0; jj < 4; jj++) {
            float v = vals[r][tid + jj * 256];
            s += v; ss += v * v;
        }
        blockReduce2(s, ss, red);
        float mean = s * (1.f / 1024.f);
        float rstd = rsqrtf(ss * (1.f / 1024.f) - mean * mean + LN_EPS);
#pragma unroll
        for (int jj = 0; jj < 4; jj++) {
            int j = tid + jj * 256;
            float v = (vals[r][j] - mean) * rstd * gvec[j] + beta[j];
            float x = elu1(v);
            size_t o = (size_t)(b0 + r) * 2048 + j;
            split_store(x, &g_ahi[o], &g_alo[o]);
        }
    }
}

// ---------------- K2: bf16x3 GEMM, per-slab 3-product schedule ----------------
// Per k-slab (32 k) load 4 tiles once (Ahi, Alo, Bhi, Blo; 8KB each, 64B rows,
// SW64 swizzle) and accumulate hi*hi + lo*hi + hi*lo. 3-stage cp.async, occ 2.
// Block tile 128x128, 8 warps = 2(M) x 4(N), warp tile 64x32.
__global__ __launch_bounds__(256, 2) void mma_gemm(int mode)
{
    extern __shared__ char smraw[];
    uint32_t base = smem_u32(smraw);

    const __nv_bfloat16 *Ahi, *Alo, *Bhi, *Blo;
    float* C;
    int lda, ldb, ldc, Kseg;
    if (mode == 0) {
        Ahi = g_ahi; Alo = g_alo; lda = 2048; Kseg = 2048;
        Bhi = g_wgru_hi; Blo = g_wgru_lo; ldb = 2048;
        C = g_parts; ldc = 3072;
    } else {
        Ahi = g_ahi + 1024; Alo = g_alo + 1024; lda = 2048; Kseg = 1024;
        Bhi = g_we1_hi; Blo = g_we1_lo; ldb = 1024;
        C = g_e1raw; ldc = 1024;
    }
    const int SLABS = Kseg >> 5;         // 32-k slabs

    int tid = threadIdx.x;
    int wid = tid >> 5, lane = tid & 31;
    int row0 = blockIdx.y * 128;
    int col0 = blockIdx.x * 128;

    const uint32_t STG = 32768u;         // per-stage: 4 tiles x 8KB
    const uint32_t T_AHI = 0u, T_ALO = 8192u, T_BHI = 16384u, T_BLO = 24576u;

    float acc[4][4][4];
#pragma unroll
    for (int i = 0; i < 4; i++)
#pragma unroll
        for (int j = 0; j < 4; j++)
#pragma unroll
            for (int q = 0; q < 4; q++) acc[i][j][q] = 0.f;

    // load one 32-k slab: 4 tiles, each 128 rows x 64B (2 cp.async/thread/tile)
    auto load_slab = [&](int s, int buf) {
        int k0 = s << 5;
        uint32_t st = base + (uint32_t)buf * STG;
#pragma unroll
        for (int i = 0; i < 2; i++) {
            int e = tid + i * 256;
            int r = e >> 2, c = e & 3;
            uint32_t so = SWZ64(r * 64 + c * 16);
            cpa16(st + T_AHI + so, Ahi + (size_t)(row0 + r) * lda + k0 + c * 8);
            cpa16(st + T_ALO + so, Alo + (size_t)(row0 + r) * lda + k0 + c * 8);
            cpa16(st + T_BHI + so, Bhi + (size_t)(col0 + r) * ldb + k0 + c * 8);
            cpa16(st + T_BLO + so, Blo + (size_t)(col0 + r) * ldb + k0 + c * 8);
        }
        cpa_commit();
    };

    int m0w = (wid & 1) * 64;
    int n0w = (wid >> 1) * 32;
    int grp = lane >> 3, rin = lane & 7;

    load_slab(0, 0);
    load_slab(1, 1);

    for (int s = 0; s < SLABS; s++) {
        int buf = s % 3;
        if (s + 1 < SLABS) cpa_wait1();
        else               cpa_wait0();
        __syncthreads();
        if (s + 2 < SLABS) load_slab(s + 2, (s + 2) % 3);

        uint32_t st = base + (uint32_t)buf * STG;
#pragma unroll
        for (int kk = 0; kk < 2; kk++) {
            // fragment smem offsets
            int a_row = rin + (grp & 1) * 8;
            int a_ch  = kk * 2 + (grp >> 1);
            int b_row = rin + (grp >> 1) * 8;
            int b_ch  = kk * 2 + (grp & 1);

            uint32_t bh[2][4], bl[2][4];
#pragma unroll
            for (int nt2 = 0; nt2 < 2; nt2++) {
                uint32_t bo = SWZ64((n0w + nt2 * 16 + b_row) * 64 + b_ch * 16);
                ldsm_x4(bh[nt2], st + T_BHI + bo);
                ldsm_x4(bl[nt2], st + T_BLO + bo);
            }
#pragma unroll
            for (int mt = 0; mt < 4; mt++) {
                uint32_t ao = SWZ64((m0w + mt * 16 + a_row) * 64 + a_ch * 16);
                uint32_t ah[4], al[4];
                ldsm_x4(ah, st + T_AHI + ao);
                ldsm_x4(al, st + T_ALO + ao);
#pragma unroll
                for (int nt = 0; nt < 4; nt++) {
                    uint32_t h0 = bh[nt >> 1][(nt & 1) * 2], h1 = bh[nt >> 1][(nt & 1) * 2 + 1];
                    uint32_t l0 = bl[nt >> 1][(nt & 1) * 2], l1 = bl[nt >> 1][(nt & 1) * 2 + 1];
                    mma16816(acc[mt][nt], ah, h0, h1);   // hi*hi
                    mma16816(acc[mt][nt], al, h0, h1);   // lo*hi
                    mma16816(acc[mt][nt], ah, l0, l1);   // hi*lo
                }
            }
        }
        __syncthreads();
    }

#pragma unroll
    for (int mt = 0; mt < 4; mt++) {
        int r0 = row0 + m0w + mt * 16 + (lane >> 2);
#pragma unroll
        for (int nt = 0; nt < 4; nt++) {
            int cc = col0 + n0w + nt * 8 + (lane & 3) * 2;
            *reinterpret_cast<float2*>(&C[(size_t)r0 * ldc + cc]) =
                make_float2(acc[mt][nt][0], acc[mt][nt][1]);
            *reinterpret_cast<float2*>(&C[(size_t)(r0 + 8) * ldc + cc]) =
                make_float2(acc[mt][nt][2], acc[mt][nt][3]);
        }
    }
}

// ---------------- K3: GRU gates ----------------
__global__ __launch_bounds__(256) void gru_kernel(
    const float* __restrict__ bgru, const float* __restrict__ ggru,
    const float* __restrict__ betag, float* __restrict__ out, int t)
{
    __shared__ float v[3072];
    __shared__ float red[64];
    int b = blockIdx.x, tid = threadIdx.x;
    const float* row = g_parts + (size_t)b * 3072;

    float loc[12];
    float s = 0.f, ss = 0.f;
#pragma unroll
    for (int jj = 0; jj < 12; jj++) {
        int j = tid + jj * 256;
        float x = row[j] + bgru[j];
        loc[jj] = x; s += x; ss += x * x;
    }
    blockReduce2(s, ss, red);
    float mean = s * (1.f / 3072.f);
    float rstd = rsqrtf(ss * (1.f / 3072.f) - mean * mean + LN_EPS);
#pragma unroll
    for (int jj = 0; jj < 12; jj++) {
        int j = tid + jj * 256;
        v[j] = (loc[jj] - mean) * rstd * ggru[j] + betag[j];
    }
    __syncthreads();

#pragma unroll
    for (int jj = 0; jj < 4; jj++) {
        int i = tid + jj * 256;
        float reset  = sigmoidf(v[i]);
        float cand   = tanhf(reset * v[i + 1024]);
        float update = sigmoidf(v[i + 2048] - 1.f);
        float dprev  = g_deter[(size_t)b * 1024 + i];
        float d = update * cand + (1.f - update) * dprev;
        g_deter[(size_t)b * 1024 + i] = d;
        size_t o = (size_t)b * 2048 + 1024 + i;
        split_store(d, &g_ahi[o], &g_alo[o]);
        out[(size_t)b * (TT * OUTW) + (size_t)t * OUTW + 128 + i] = d;
    }
}

// ---------------- K5: e1 LN+ELU ----------------
__global__ __launch_bounds__(256) void e1ln_kernel(
    const float* __restrict__ be1, const float* __restrict__ ge1,
    const float* __restrict__ betae1)
{
    __shared__ float red[64];
    int b = blockIdx.x, tid = threadIdx.x;
    float loc[4];
    float s = 0.f, ss = 0.f;
#pragma unroll
    for (int jj = 0; jj < 4; jj++) {
        int j = tid + jj * 256;
        float x = g_e1raw[(size_t)b * 1024 + j] + be1[j];
        loc[jj] = x; s += x; ss += x * x;
    }
    blockReduce2(s, ss, red);
    float mean = s * (1.f / 1024.f);
    float rstd = rsqrtf(ss * (1.f / 1024.f) - mean * mean + LN_EPS);
#pragma unroll
    for (int jj = 0; jj < 4; jj++) {
        int j = tid + jj * 256;
        float v = (loc[jj] - mean) * rstd * ge1[j] + betae1[j];
        g_h[(size_t)b * 1024 + j] = elu1(v);
    }
}

// ---------------- K6: e2 GEMM + stats ----------------
__global__ __launch_bounds__(256) void e2_kernel(
    const float* __restrict__ W, const float* __restrict__ bias,
    float* __restrict__ out, int t)
{
    __shared__ float hs[16][33];
    __shared__ float ws[32][128];
    int tid = threadIdx.x;
    int r0 = blockIdx.x * 16;
    int col = tid & 127, rl = tid >> 7;
    float acc[8];
#pragma unroll
    for (int q = 0; q < 8; q++) acc[q] = 0.f;

    for (int k0 = 0; k0 < 1024; k0 += 32) {
        for (int e = tid; e < 512; e += 256) {
            int rr = e >> 5, kk = e & 31;
            hs[rr][kk] = g_h[(size_t)(r0 + rr) * 1024 + k0 + kk];
        }
#pragma unroll
        for (int e = tid; e < 4096; e += 256) {
            int kk = e >> 7, cc = e & 127;
            ws[kk][cc] = W[(size_t)(k0 + kk) * 128 + cc];
        }
        __syncthreads();
#pragma unroll
        for (int kk = 0; kk < 32; kk++) {
            float wv = ws[kk][col];
#pragma unroll
            for (int q = 0; q < 8; q++)
                acc[q] = fmaf(hs[rl + 2 * q][kk], wv, acc[q]);
        }
        __syncthreads();
    }

    float bv = bias[col];
#pragma unroll
    for (int q = 0; q < 8; q++) {
        int r = r0 + rl + 2 * q;
        float sv = acc[q] + bv;
        if (col < 64) {
            g_stoch[(size_t)r * STOCH + col] = sv;
            out[(size_t)r * (TT * OUTW) + (size_t)t * OUTW + col] = sv;
        } else {
            float sp = fmaxf(sv, 0.f) + log1pf(expf(-fabsf(sv)));
            out[(size_t)r * (TT * OUTW) + (size_t)t * OUTW + col] = sp + 0.1f;
        }
    }
}

// ---------------- launcher ----------------
#define MMA_SMEM 98304

extern "C" void kernel_launch(void* const* d_in, const int* in_sizes, int n_in,
                              void* d_out, int out_size)
{
    const float* action   = (const float*)d_in[0];
    const float* W_img    = (const float*)d_in[1];
    const float* b_img    = (const float*)d_in[2];
    const float* g_img    = (const float*)d_in[3];
    const float* beta_img = (const float*)d_in[4];
    const float* W_gru    = (const float*)d_in[5];
    const float* b_gru    = (const float*)d_in[6];
    const float* g_gru    = (const float*)d_in[7];
    const float* beta_gru = (const float*)d_in[8];
    const float* W_e1     = (const float*)d_in[9];    // [5,1024,1024] -> slice 0
    const float* b_e1     = (const float*)d_in[10];
    const float* g_e1     = (const float*)d_in[11];
    const float* beta_e1  = (const float*)d_in[12];
    const float* W_e2     = (const float*)d_in[13];   // [5,1024,128] -> slice 0
    const float* b_e2     = (const float*)d_in[14];
    float* out = (float*)d_out;

    cudaFuncSetAttribute(mma_gemm, cudaFuncAttributeMaxDynamicSharedMemorySize, MMA_SMEM);

    init_kernel<<<(BATCH * DETER + 255) / 256, 256>>>();

    __nv_bfloat16 *wgh, *wgl, *weh, *wel;
    cudaGetSymbolAddress((void**)&wgh, g_wgru_hi);
    cudaGetSymbolAddress((void**)&wgl, g_wgru_lo);
    cudaGetSymbolAddress((void**)&weh, g_we1_hi);
    cudaGetSymbolAddress((void**)&wel, g_we1_lo);
    wprep_kernel<<<dim3(3072 / 32, 2048 / 32), 256>>>(W_gru, wgh, wgl, 2048, 3072);
    wprep_kernel<<<dim3(1024 / 32, 1024 / 32), 256>>>(W_e1, weh, wel, 1024, 1024);

    for (int t = 0; t < TT; t++) {
        img_kernel<<<BATCH / 8, 256>>>(action, W_img, b_img, g_img, beta_img, t);
        mma_gemm<<<dim3(3072 / 128, BATCH / 128), 256, MMA_SMEM>>>(0);
        gru_kernel<<<BATCH, 256>>>(b_gru, g_gru, beta_gru, out, t);
        mma_gemm<<<dim3(1024 / 128, BATCH / 128), 256, MMA_SMEM>>>(1);
        e1ln_kernel<<<BATCH, 256>>>(b_e1, g_e1, beta_e1);
        e2_kernel<<<BATCH / 16, 256>>>(W_e2, b_e2, out, t);
    }
}